// round 1
// baseline (speedup 1.0000x reference)
#include <cuda_runtime.h>
#include <cstdint>

#define S_LEN 1024
#define DIM   1024
#define BATCH 64
#define MTOT  (BATCH * S_LEN)   // 65536 rows

// Scratch (no allocations allowed)
__device__ float g_target[BATCH * DIM];       // input @ W_q^T  (64 x 1024)
__device__ float g_epart[8 * MTOT];           // per-nblock energy partials

__device__ __forceinline__ uint32_t f2tf(float x) {
    uint32_t r;
    asm("cvt.rna.tf32.f32 %0, %1;" : "=r"(r) : "f"(x));
    return r;
}

__device__ __forceinline__ void mma_tf32(float c[4], const uint32_t a[4], const uint32_t b[2]) {
    asm volatile(
        "mma.sync.aligned.m16n8k8.row.col.f32.tf32.tf32.f32 "
        "{%0,%1,%2,%3},{%4,%5,%6,%7},{%8,%9},{%0,%1,%2,%3};"
        : "+f"(c[0]), "+f"(c[1]), "+f"(c[2]), "+f"(c[3])
        : "r"(a[0]), "r"(a[1]), "r"(a[2]), "r"(a[3]), "r"(b[0]), "r"(b[1]));
}

// ---------------------------------------------------------------------------
// Kernel A: target = input @ W_q^T   (64 x 1024, K=1024)
// grid = 64 blocks (16 n-columns each), 256 threads
// ---------------------------------------------------------------------------
__global__ void __launch_bounds__(256) target_kernel(const float* __restrict__ input,
                                                     const float* __restrict__ Wq) {
    __shared__ float Ain[64][33];
    __shared__ float Wqs[32][20];   // [k][n], padded stride 20 for 16B-aligned float4

    int t  = threadIdx.x;
    int n0 = blockIdx.x * 16;
    int r  = t & 63;          // batch row
    int c0 = (t >> 6) * 4;    // 4 n-columns per thread

    float acc[4] = {0.f, 0.f, 0.f, 0.f};

    for (int k0 = 0; k0 < DIM; k0 += 32) {
#pragma unroll
        for (int i = 0; i < 2; i++) {
            int e  = t + i * 256;
            int rr = e >> 3, cc = (e & 7) * 4;
            float4 v = *(const float4*)(input + (size_t)rr * DIM + k0 + cc);
            Ain[rr][cc] = v.x; Ain[rr][cc + 1] = v.y; Ain[rr][cc + 2] = v.z; Ain[rr][cc + 3] = v.w;
        }
        if (t < 128) {
            int rr = t >> 3, cc = (t & 7) * 4;
            float4 v = *(const float4*)(Wq + (size_t)(n0 + rr) * DIM + k0 + cc);
            Wqs[cc][rr] = v.x; Wqs[cc + 1][rr] = v.y; Wqs[cc + 2][rr] = v.z; Wqs[cc + 3][rr] = v.w;
        }
        __syncthreads();
#pragma unroll
        for (int kk = 0; kk < 32; kk++) {
            float a  = Ain[r][kk];
            float4 w = *(const float4*)&Wqs[kk][c0];
            acc[0] += a * w.x; acc[1] += a * w.y; acc[2] += a * w.z; acc[3] += a * w.w;
        }
        __syncthreads();
    }
    float4 o = {acc[0], acc[1], acc[2], acc[3]};
    *(float4*)(g_target + (size_t)r * DIM + n0 + c0) = o;
}

// ---------------------------------------------------------------------------
// Kernel B: precompute = context @ W_pre^T + b_pre   (tf32 mma)
//           fused: energy partials = sum_n W_v[n]*tanh(pre + target + cov*W_cov)
// Tile 128x128x32, 256 threads (8 warps, 2x4), grid (512, 8)
// ---------------------------------------------------------------------------
__global__ void __launch_bounds__(256) main_kernel(const float* __restrict__ ctx,
                                                   const float* __restrict__ Wpre,
                                                   const float* __restrict__ bpre,
                                                   const float* __restrict__ Wv,
                                                   const float* __restrict__ Wcov,
                                                   const float* __restrict__ cov,
                                                   float* __restrict__ pre_out) {
    __shared__ uint32_t As[128][36];   // pad 36: conflict-free frag loads
    __shared__ uint32_t Bs[128][36];
    __shared__ float    esum[2][64][4];

    int tid  = threadIdx.x;
    int lane = tid & 31, warp = tid >> 5;
    int wm = warp >> 2, wn = warp & 3;
    int m0 = blockIdx.x * 128;
    int n0 = blockIdx.y * 128;
    int gr = lane >> 2, gc = lane & 3;

    float c[4][4][4];
#pragma unroll
    for (int i = 0; i < 4; i++)
#pragma unroll
        for (int j = 0; j < 4; j++)
#pragma unroll
            for (int q = 0; q < 4; q++) c[i][j][q] = 0.f;

    int lr = tid >> 3;         // 0..31
    int lc = (tid & 7) * 4;    // 0..28

    for (int k0 = 0; k0 < DIM; k0 += 32) {
#pragma unroll
        for (int i = 0; i < 4; i++) {
            float4 v = *(const float4*)(ctx + (size_t)(m0 + lr + i * 32) * DIM + k0 + lc);
            uint32_t* p = &As[lr + i * 32][lc];
            p[0] = f2tf(v.x); p[1] = f2tf(v.y); p[2] = f2tf(v.z); p[3] = f2tf(v.w);
        }
#pragma unroll
        for (int i = 0; i < 4; i++) {
            float4 v = *(const float4*)(Wpre + (size_t)(n0 + lr + i * 32) * DIM + k0 + lc);
            uint32_t* p = &Bs[lr + i * 32][lc];
            p[0] = f2tf(v.x); p[1] = f2tf(v.y); p[2] = f2tf(v.z); p[3] = f2tf(v.w);
        }
        __syncthreads();
#pragma unroll
        for (int kk = 0; kk < 32; kk += 8) {
            uint32_t af[4][4], bf[4][2];
#pragma unroll
            for (int mt = 0; mt < 4; mt++) {
                int r = wm * 64 + mt * 16 + gr;
                af[mt][0] = As[r][kk + gc];
                af[mt][1] = As[r + 8][kk + gc];
                af[mt][2] = As[r][kk + gc + 4];
                af[mt][3] = As[r + 8][kk + gc + 4];
            }
#pragma unroll
            for (int nt = 0; nt < 4; nt++) {
                int cn = wn * 32 + nt * 8 + gr;
                bf[nt][0] = Bs[cn][kk + gc];
                bf[nt][1] = Bs[cn][kk + gc + 4];
            }
#pragma unroll
            for (int mt = 0; mt < 4; mt++)
#pragma unroll
                for (int nt = 0; nt < 4; nt++)
                    mma_tf32(c[mt][nt], af[mt], bf[nt]);
        }
        __syncthreads();
    }

    // ---- fused epilogue ----
    int b = m0 >> 10;                       // 128 | 1024, so one batch per block
    const float* tgt = g_target + (size_t)b * DIM;

#pragma unroll
    for (int mt = 0; mt < 4; mt++) {
#pragma unroll
        for (int half = 0; half < 2; half++) {
            int m = m0 + wm * 64 + mt * 16 + gr + half * 8;
            float covm = cov[m];
            float acc = 0.f;
#pragma unroll
            for (int nt = 0; nt < 4; nt++) {
                int n = n0 + wn * 32 + nt * 8 + gc * 2;
                float v0 = c[mt][nt][half * 2 + 0] + bpre[n];
                float v1 = c[mt][nt][half * 2 + 1] + bpre[n + 1];
                float2 st = {v0, v1};
                *(float2*)(pre_out + (size_t)m * DIM + n) = st;
                float t0 = tanhf(v0 + tgt[n]     + covm * Wcov[n]);
                float t1 = tanhf(v1 + tgt[n + 1] + covm * Wcov[n + 1]);
                acc += Wv[n] * t0 + Wv[n + 1] * t1;
            }
            acc += __shfl_xor_sync(0xffffffffu, acc, 1);
            acc += __shfl_xor_sync(0xffffffffu, acc, 2);
            if (gc == 0) esum[wm][mt * 16 + gr + half * 8][wn] = acc;
        }
    }
    __syncthreads();
    if (tid < 128) {
        int wmx = tid >> 6, rr = tid & 63;
        float e = esum[wmx][rr][0] + esum[wmx][rr][1] + esum[wmx][rr][2] + esum[wmx][rr][3];
        g_epart[(size_t)blockIdx.y * MTOT + m0 + wmx * 64 + rr] = e;
    }
}

// ---------------------------------------------------------------------------
// Kernel C: softmax over S per batch + coverage update
// grid = 64, 256 threads
// ---------------------------------------------------------------------------
__global__ void __launch_bounds__(256) softmax_kernel(const float* __restrict__ cov,
                                                      float* __restrict__ score,
                                                      float* __restrict__ cov_new) {
    __shared__ float e[1024];
    __shared__ float red[8];
    int b = blockIdx.x, t = threadIdx.x;

    float lmax = -1e30f;
    for (int i = t; i < 1024; i += 256) {
        float s = 0.f;
#pragma unroll
        for (int p = 0; p < 8; p++) s += g_epart[(size_t)p * MTOT + b * 1024 + i];
        e[i] = s;
        lmax = fmaxf(lmax, s);
    }
#pragma unroll
    for (int o = 16; o > 0; o >>= 1) lmax = fmaxf(lmax, __shfl_xor_sync(~0u, lmax, o));
    if ((t & 31) == 0) red[t >> 5] = lmax;
    __syncthreads();
    float bmax = fmaxf(fmaxf(fmaxf(red[0], red[1]), fmaxf(red[2], red[3])),
                       fmaxf(fmaxf(red[4], red[5]), fmaxf(red[6], red[7])));
    __syncthreads();

    float lsum = 0.f;
    for (int i = t; i < 1024; i += 256) {
        float ex = expf(e[i] - bmax);
        e[i] = ex;
        lsum += ex;
    }
#pragma unroll
    for (int o = 16; o > 0; o >>= 1) lsum += __shfl_xor_sync(~0u, lsum, o);
    if ((t & 31) == 0) red[t >> 5] = lsum;
    __syncthreads();
    float total = red[0] + red[1] + red[2] + red[3] + red[4] + red[5] + red[6] + red[7];
    float inv = 1.f / total;
    for (int i = t; i < 1024; i += 256) {
        float sc = e[i] * inv;
        score[b * 1024 + i] = sc;
        cov_new[b * 1024 + i] = cov[b * 1024 + i] + sc;
    }
}

// ---------------------------------------------------------------------------
// Kernel D: weightedContext[b,d] = sum_s score[b,s] * context[b,s,d]
// grid = (64, 8), 128 threads
// ---------------------------------------------------------------------------
__global__ void __launch_bounds__(128) wctx_kernel(const float* __restrict__ ctx,
                                                   const float* __restrict__ score,
                                                   float* __restrict__ out) {
    __shared__ float sc[1024];
    int b = blockIdx.x, dc = blockIdx.y, t = threadIdx.x;
    for (int i = t; i < 1024; i += 128) sc[i] = score[b * 1024 + i];
    __syncthreads();
    int d = dc * 128 + t;
    const float* cp = ctx + (size_t)b * S_LEN * DIM + d;
    float a0 = 0.f, a1 = 0.f, a2 = 0.f, a3 = 0.f;
    for (int s = 0; s < 1024; s += 4) {
        a0 += sc[s + 0] * cp[(size_t)(s + 0) * DIM];
        a1 += sc[s + 1] * cp[(size_t)(s + 1) * DIM];
        a2 += sc[s + 2] * cp[(size_t)(s + 2) * DIM];
        a3 += sc[s + 3] * cp[(size_t)(s + 3) * DIM];
    }
    out[b * 1024 + d] = (a0 + a1) + (a2 + a3);
}

// ---------------------------------------------------------------------------
// Launch
// Inputs (metadata order): input, context, coverage_acc, W_pre, b_pre, W_q, W_v, W_cov
// Output: [weightedContext (64*1024) | score (64*1024) | coverage_new (64*1024) |
//          precompute (64*1024*1024)]
// ---------------------------------------------------------------------------
extern "C" void kernel_launch(void* const* d_in, const int* in_sizes, int n_in,
                              void* d_out, int out_size) {
    const float* input = (const float*)d_in[0];
    const float* ctx   = (const float*)d_in[1];
    const float* cov   = (const float*)d_in[2];
    const float* Wpre  = (const float*)d_in[3];
    const float* bpre  = (const float*)d_in[4];
    const float* Wq    = (const float*)d_in[5];
    const float* Wv    = (const float*)d_in[6];
    const float* Wcov  = (const float*)d_in[7];

    float* out     = (float*)d_out;
    float* wc      = out;
    float* score   = out + 65536;
    float* cov_new = out + 131072;
    float* pre_out = out + 196608;

    target_kernel<<<64, 256>>>(input, Wq);

    dim3 gb(512, 8);
    main_kernel<<<gb, 256>>>(ctx, Wpre, bpre, Wv, Wcov, cov, pre_out);

    softmax_kernel<<<64, 256>>>(cov, score, cov_new);

    dim3 gd(64, 8);
    wctx_kernel<<<gd, 128>>>(ctx, score, wc);
}

// round 3
// speedup vs baseline: 1.3030x; 1.3030x over previous
#include <cuda_runtime.h>
#include <cstdint>

#define S_LEN 1024
#define DIM   1024
#define BATCH 64
#define MTOT  (BATCH * S_LEN)   // 65536 rows

// ---------------- scratch (no allocations allowed) ----------------
__device__ float g_target[BATCH * DIM];        // input @ W_q^T (64 x 1024)
__device__ float g_epart[4 * MTOT];            // per n-chunk energy partials
__device__ float g_wcpart[4 * BATCH * DIM];    // wctx s-split partials

__device__ __forceinline__ uint32_t smem_u32(const void* p) {
    uint32_t a;
    asm("{ .reg .u64 t; cvta.to.shared.u64 t, %1; cvt.u32.u64 %0, t; }" : "=r"(a) : "l"(p));
    return a;
}
__device__ __forceinline__ void cp16(uint32_t dst, const void* src) {
    asm volatile("cp.async.ca.shared.global [%0], [%1], 16;" :: "r"(dst), "l"(src));
}
#define CP_COMMIT() asm volatile("cp.async.commit_group;" ::: "memory")
#define CP_WAIT2()  asm volatile("cp.async.wait_group 2;" ::: "memory")

__device__ __forceinline__ void mma_tf32(float c[4], const uint32_t a[4], const uint32_t b[2]) {
    asm volatile(
        "mma.sync.aligned.m16n8k8.row.col.f32.tf32.tf32.f32 "
        "{%0,%1,%2,%3},{%4,%5,%6,%7},{%8,%9},{%0,%1,%2,%3};"
        : "+f"(c[0]), "+f"(c[1]), "+f"(c[2]), "+f"(c[3])
        : "r"(a[0]), "r"(a[1]), "r"(a[2]), "r"(a[3]), "r"(b[0]), "r"(b[1]));
}

// ---------------- SMEM layout for main kernel ----------------
// A tile: 128 rows x 32 k floats, padded row stride 36 floats (144 B)
// B tile: 256 rows x 32 k floats, same stride
static constexpr int A_ST   = 128 * 36 * 4;          // 18432 B / stage
static constexpr int B_ST   = 256 * 36 * 4;          // 36864 B / stage
static constexpr int OFF_A  = 0;
static constexpr int OFF_B  = 3 * A_ST;              // 55296
static constexpr int OFF_P  = OFF_B + 3 * B_ST;      // 165888 (4 x 256 floats)
static constexpr int OFF_E  = OFF_P + 4096;          // 169984 (esum 2x64x4)
static constexpr int SMEM_TOTAL = OFF_E + 2048;      // 172032

// ---------------------------------------------------------------------------
// Kernel A: target = input @ W_q^T   (64 x 1024, K=1024)
// ---------------------------------------------------------------------------
__global__ void __launch_bounds__(256) target_kernel(const float* __restrict__ input,
                                                     const float* __restrict__ Wq) {
    __shared__ float Ain[64][33];
    __shared__ float Wqs[32][20];

    int t  = threadIdx.x;
    int n0 = blockIdx.x * 16;
    int r  = t & 63;
    int c0 = (t >> 6) * 4;

    float acc[4] = {0.f, 0.f, 0.f, 0.f};

    for (int k0 = 0; k0 < DIM; k0 += 32) {
#pragma unroll
        for (int i = 0; i < 2; i++) {
            int e  = t + i * 256;
            int rr = e >> 3, cc = (e & 7) * 4;
            float4 v = *(const float4*)(input + (size_t)rr * DIM + k0 + cc);
            Ain[rr][cc] = v.x; Ain[rr][cc + 1] = v.y; Ain[rr][cc + 2] = v.z; Ain[rr][cc + 3] = v.w;
        }
        if (t < 128) {
            int rr = t >> 3, cc = (t & 7) * 4;
            float4 v = *(const float4*)(Wq + (size_t)(n0 + rr) * DIM + k0 + cc);
            Wqs[cc][rr] = v.x; Wqs[cc + 1][rr] = v.y; Wqs[cc + 2][rr] = v.z; Wqs[cc + 3][rr] = v.w;
        }
        __syncthreads();
#pragma unroll
        for (int kk = 0; kk < 32; kk++) {
            float a  = Ain[r][kk];
            float4 w = *(const float4*)&Wqs[kk][c0];
            acc[0] += a * w.x; acc[1] += a * w.y; acc[2] += a * w.z; acc[3] += a * w.w;
        }
        __syncthreads();
    }
    float4 o = {acc[0], acc[1], acc[2], acc[3]};
    *(float4*)(g_target + (size_t)r * DIM + n0 + c0) = o;
}

// ---------------------------------------------------------------------------
// Kernel B: precompute = context @ W_pre^T + b_pre  via mma.sync tf32,
//           cp.async 3-stage pipeline, tile 128m x 256n x 32k.
//           Fused epilogue: store precompute, energy partials.
// grid (512 m-tiles, 4 n-chunks), 256 threads (8 warps, 2x4)
// ---------------------------------------------------------------------------
__global__ void __launch_bounds__(256, 1) main_mma(const float* __restrict__ ctx,
                                                   const float* __restrict__ Wpre,
                                                   const float* __restrict__ bpre,
                                                   const float* __restrict__ Wv,
                                                   const float* __restrict__ Wcov,
                                                   const float* __restrict__ cov,
                                                   float* __restrict__ pre_out) {
    extern __shared__ char smem[];
    const uint32_t sb = smem_u32(smem);
    const int tid  = threadIdx.x;
    const int lane = tid & 31, warp = tid >> 5;
    const int wm = warp >> 2, wn = warp & 3;       // 2 x 4 warp grid
    const int gr = lane >> 2, gc = lane & 3;
    const int m0 = blockIdx.x * 128;
    const int n0 = blockIdx.y * 256;

    // cp.async issue helper: one K-chunk (32 cols) of A(128 rows) + B(256 rows)
    const int lrow = tid >> 3;        // 0..31
    const int lseg = tid & 7;         // 0..7 (16B segment within 128B row)

    auto issue_chunk = [&](int kc, int st) {
        const int k0 = kc * 32;
#pragma unroll
        for (int i = 0; i < 4; i++) {
            int row = lrow + i * 32;
            cp16(sb + OFF_A + st * A_ST + row * 144 + lseg * 16,
                 ctx + (size_t)(m0 + row) * DIM + k0 + lseg * 4);
        }
#pragma unroll
        for (int i = 0; i < 8; i++) {
            int row = lrow + i * 32;
            cp16(sb + OFF_B + st * B_ST + row * 144 + lseg * 16,
                 Wpre + (size_t)(n0 + row) * DIM + k0 + lseg * 4);
        }
    };

    float c[4][8][4];
#pragma unroll
    for (int i = 0; i < 4; i++)
#pragma unroll
        for (int j = 0; j < 8; j++)
#pragma unroll
            for (int q = 0; q < 4; q++) c[i][j][q] = 0.f;

    // prologue: chunks 0,1 -> stages 0,1
    issue_chunk(0, 0); CP_COMMIT();
    issue_chunk(1, 1); CP_COMMIT();

#pragma unroll 1
    for (int kc = 0; kc < 32; kc++) {
        if (kc + 2 < 32) issue_chunk(kc + 2, (kc + 2) % 3);
        CP_COMMIT();           // unconditional: keeps group accounting uniform
        CP_WAIT2();            // chunk kc's group complete
        __syncthreads();

        const int st = kc % 3;
        const uint32_t* As = (const uint32_t*)(smem + OFF_A + st * A_ST);
        const uint32_t* Bs = (const uint32_t*)(smem + OFF_B + st * B_ST);

#pragma unroll
        for (int kk = 0; kk < 4; kk++) {
            const int kb = kk * 8;
            uint32_t a[4][4], b[8][2];
#pragma unroll
            for (int mt = 0; mt < 4; mt++) {
                const int r = wm * 64 + mt * 16 + gr;
                a[mt][0] = As[r * 36 + kb + gc];
                a[mt][1] = As[(r + 8) * 36 + kb + gc];
                a[mt][2] = As[r * 36 + kb + gc + 4];
                a[mt][3] = As[(r + 8) * 36 + kb + gc + 4];
            }
#pragma unroll
            for (int nt = 0; nt < 8; nt++) {
                const int cn = wn * 64 + nt * 8 + gr;
                b[nt][0] = Bs[cn * 36 + kb + gc];
                b[nt][1] = Bs[cn * 36 + kb + gc + 4];
            }
#pragma unroll
            for (int mt = 0; mt < 4; mt++)
#pragma unroll
                for (int nt = 0; nt < 8; nt++)
                    mma_tf32(c[mt][nt], a[mt], b[nt]);
        }
        __syncthreads();       // protect stage reuse before next issue
    }

    // ---- epilogue params to smem ----
    float* shp = (float*)(smem + OFF_P);
    const float* tgt = g_target + (size_t)(m0 >> 10) * DIM;
    {
        int i = tid;                    // 256 threads, 256 cols
        shp[i]       = bpre[n0 + i];
        shp[256 + i] = tgt[n0 + i];
        shp[512 + i] = Wv[n0 + i];
        shp[768 + i] = Wcov[n0 + i];
    }
    __syncthreads();

    // ---- fused epilogue ----
    float* shep = (float*)(smem + OFF_E);    // esum[2][64][4]
#pragma unroll
    for (int mt = 0; mt < 4; mt++) {
#pragma unroll
        for (int half = 0; half < 2; half++) {
            const int rl = wm * 64 + mt * 16 + gr + half * 8;   // local row 0..127
            const int m  = m0 + rl;
            const float covm = cov[m];
            float eacc = 0.f;
            float* op = pre_out + (size_t)m * DIM + n0;
#pragma unroll
            for (int nt = 0; nt < 8; nt++) {
                const int n = wn * 64 + nt * 8 + gc * 2;
                float v0 = c[mt][nt][half * 2 + 0] + shp[n];
                float v1 = c[mt][nt][half * 2 + 1] + shp[n + 1];
                float2 st = {v0, v1};
                *(float2*)(op + n) = st;
                eacc += shp[512 + n]     * tanhf(v0 + shp[256 + n]     + covm * shp[768 + n]);
                eacc += shp[512 + n + 1] * tanhf(v1 + shp[256 + n + 1] + covm * shp[768 + n + 1]);
            }
            eacc += __shfl_xor_sync(0xffffffffu, eacc, 1);
            eacc += __shfl_xor_sync(0xffffffffu, eacc, 2);
            if (gc == 0) shep[(wm * 64 + mt * 16 + gr + half * 8) * 4 + wn] = eacc;
        }
    }
    __syncthreads();
    if (tid < 128) {
        float e = shep[tid * 4] + shep[tid * 4 + 1] + shep[tid * 4 + 2] + shep[tid * 4 + 3];
        g_epart[(size_t)blockIdx.y * MTOT + m0 + tid] = e;
    }
}

// ---------------------------------------------------------------------------
// Kernel C: softmax over S per batch + coverage update (4 energy partials)
// ---------------------------------------------------------------------------
__global__ void __launch_bounds__(256) softmax_kernel(const float* __restrict__ cov,
                                                      float* __restrict__ score,
                                                      float* __restrict__ cov_new) {
    __shared__ float e[1024];
    __shared__ float red[8];
    int b = blockIdx.x, t = threadIdx.x;

    float lmax = -1e30f;
    for (int i = t; i < 1024; i += 256) {
        float s = g_epart[b * 1024 + i] + g_epart[MTOT + b * 1024 + i] +
                  g_epart[2 * MTOT + b * 1024 + i] + g_epart[3 * MTOT + b * 1024 + i];
        e[i] = s;
        lmax = fmaxf(lmax, s);
    }
#pragma unroll
    for (int o = 16; o > 0; o >>= 1) lmax = fmaxf(lmax, __shfl_xor_sync(~0u, lmax, o));
    if ((t & 31) == 0) red[t >> 5] = lmax;
    __syncthreads();
    float bmax = fmaxf(fmaxf(fmaxf(red[0], red[1]), fmaxf(red[2], red[3])),
                       fmaxf(fmaxf(red[4], red[5]), fmaxf(red[6], red[7])));
    __syncthreads();

    float lsum = 0.f;
    for (int i = t; i < 1024; i += 256) {
        float ex = expf(e[i] - bmax);
        e[i] = ex;
        lsum += ex;
    }
#pragma unroll
    for (int o = 16; o > 0; o >>= 1) lsum += __shfl_xor_sync(~0u, lsum, o);
    if ((t & 31) == 0) red[t >> 5] = lsum;
    __syncthreads();
    float total = red[0] + red[1] + red[2] + red[3] + red[4] + red[5] + red[6] + red[7];
    float inv = 1.f / total;
    for (int i = t; i < 1024; i += 256) {
        float sc = e[i] * inv;
        score[b * 1024 + i] = sc;
        cov_new[b * 1024 + i] = cov[b * 1024 + i] + sc;
    }
}

// ---------------------------------------------------------------------------
// Kernel D: weightedContext partials, s split by 4  (grid (64,8,4), 128 thr)
// ---------------------------------------------------------------------------
__global__ void __launch_bounds__(128) wctx_part(const float* __restrict__ ctx,
                                                 const float* __restrict__ score) {
    __shared__ float sc[256];
    int b = blockIdx.x, dc = blockIdx.y, sz = blockIdx.z, t = threadIdx.x;
    for (int i = t; i < 256; i += 128) sc[i] = score[b * 1024 + sz * 256 + i];
    __syncthreads();
    int d = dc * 128 + t;
    const float* cp = ctx + ((size_t)b * S_LEN + sz * 256) * DIM + d;
    float a0 = 0.f, a1 = 0.f, a2 = 0.f, a3 = 0.f;
    float a4 = 0.f, a5 = 0.f, a6 = 0.f, a7 = 0.f;
    for (int s = 0; s < 256; s += 8) {
        a0 += sc[s + 0] * cp[(size_t)(s + 0) * DIM];
        a1 += sc[s + 1] * cp[(size_t)(s + 1) * DIM];
        a2 += sc[s + 2] * cp[(size_t)(s + 2) * DIM];
        a3 += sc[s + 3] * cp[(size_t)(s + 3) * DIM];
        a4 += sc[s + 4] * cp[(size_t)(s + 4) * DIM];
        a5 += sc[s + 5] * cp[(size_t)(s + 5) * DIM];
        a6 += sc[s + 6] * cp[(size_t)(s + 6) * DIM];
        a7 += sc[s + 7] * cp[(size_t)(s + 7) * DIM];
    }
    g_wcpart[((size_t)sz * BATCH + b) * DIM + d] =
        ((a0 + a1) + (a2 + a3)) + ((a4 + a5) + (a6 + a7));
}

__global__ void __launch_bounds__(256) wctx_reduce(float* __restrict__ wc) {
    int i = blockIdx.x * 256 + threadIdx.x;
    wc[i] = g_wcpart[i] + g_wcpart[65536 + i] + g_wcpart[131072 + i] + g_wcpart[196608 + i];
}

// ---------------------------------------------------------------------------
// Launch.  Inputs: input, context, coverage_acc, W_pre, b_pre, W_q, W_v, W_cov
// Output: [wc (64k) | score (64k) | cov_new (64k) | precompute (64M)]
// ---------------------------------------------------------------------------
extern "C" void kernel_launch(void* const* d_in, const int* in_sizes, int n_in,
                              void* d_out, int out_size) {
    const float* input = (const float*)d_in[0];
    const float* ctx   = (const float*)d_in[1];
    const float* cov   = (const float*)d_in[2];
    const float* Wpre  = (const float*)d_in[3];
    const float* bpre  = (const float*)d_in[4];
    const float* Wq    = (const float*)d_in[5];
    const float* Wv    = (const float*)d_in[6];
    const float* Wcov  = (const float*)d_in[7];

    float* out     = (float*)d_out;
    float* wc      = out;
    float* score   = out + 65536;
    float* cov_new = out + 131072;
    float* pre_out = out + 196608;

    static bool attr_set = false;
    if (!attr_set) {
        cudaFuncSetAttribute(main_mma, cudaFuncAttributeMaxDynamicSharedMemorySize, SMEM_TOTAL);
        attr_set = true;
    }

    target_kernel<<<64, 256>>>(input, Wq);

    dim3 gb(512, 4);
    main_mma<<<gb, 256, SMEM_TOTAL>>>(ctx, Wpre, bpre, Wv, Wcov, cov, pre_out);

    softmax_kernel<<<64, 256>>>(cov, score, cov_new);

    dim3 gd(64, 8, 4);
    wctx_part<<<gd, 128>>>(ctx, score);
    wctx_reduce<<<256, 256>>>(wc);
}